// round 1
// baseline (speedup 1.0000x reference)
#include <cuda_runtime.h>

#define NN 100000
#define NE 1250000
#define D  64
#define NB 16

// Scratch (no allocs allowed) — zeroed every launch via cudaMemsetAsync.
__device__ float g_h[(size_t)NN * D];   // sum of x[src] per dst node
__device__ float g_deg[NN];             // in-degree (float)
__device__ float g_Wm[D * D];           // reconstructed W_msg  [i][o]
__device__ float g_Ws[D * D];           // reconstructed W_self [i][o]
__device__ float g_bm[D];
__device__ float g_bs[D];

// ---------------------------------------------------------------------------
// Kernel 1: reconstruct weights from bases (tiny: 4160 threads)
// ---------------------------------------------------------------------------
__global__ void k_weights(const float* __restrict__ bmw, const float* __restrict__ bmb,
                          const float* __restrict__ bsw, const float* __restrict__ bsb,
                          const float* __restrict__ lc) {
    __shared__ float c[NB];
    if (threadIdx.x < NB) c[threadIdx.x] = lc[threadIdx.x];
    __syncthreads();
    int idx = blockIdx.x * blockDim.x + threadIdx.x;
    if (idx < D * D) {
        float wm = 0.f, ws = 0.f;
        #pragma unroll
        for (int b = 0; b < NB; b++) {
            wm = fmaf(bmw[idx * NB + b], c[b], wm);
            ws = fmaf(bsw[idx * NB + b], c[b], ws);
        }
        g_Wm[idx] = wm;
        g_Ws[idx] = ws;
    } else if (idx < D * D + D) {
        int o = idx - D * D;
        float bm = 0.f, bs = 0.f;
        #pragma unroll
        for (int b = 0; b < NB; b++) {
            bm = fmaf(bmb[o * NB + b], c[b], bm);
            bs = fmaf(bsb[o * NB + b], c[b], bs);
        }
        g_bm[o] = bm;
        g_bs[o] = bs;
    }
}

// ---------------------------------------------------------------------------
// Kernel 2: scatter-add raw x rows.  16 threads per edge, float4 per thread,
// vector reduction (red.global.add.v4.f32, sm_90+).
// ---------------------------------------------------------------------------
__global__ void k_scatter(const float4* __restrict__ x4, const int* __restrict__ ei) {
    unsigned t = blockIdx.x * blockDim.x + threadIdx.x;
    unsigned e = t >> 4;
    if (e >= NE) return;
    int j = t & 15;
    int src = __ldg(ei + e);
    int dst = __ldg(ei + NE + e);
    float4 v = __ldg(x4 + (size_t)src * (D / 4) + j);
    float* p = g_h + (size_t)dst * D + j * 4;
    asm volatile("red.global.add.v4.f32 [%0], {%1,%2,%3,%4};"
                 :: "l"(p), "f"(v.x), "f"(v.y), "f"(v.z), "f"(v.w)
                 : "memory");
    if (j == 0) atomicAdd(&g_deg[dst], 1.0f);
}

// ---------------------------------------------------------------------------
// Kernel 3: out = normalize( h @ Wm + x @ Ws + deg*bm + bs )
// Tiled: 64 nodes x 64 cols per block, W ([128][64]) resident in shared,
// inputs concat([h|x]) as a [64][128] tile.  256 threads, each computes
// a 4-node x 4-col micro tile (16 FMAs per k-step per thread).
// ---------------------------------------------------------------------------
#define IN_STRIDE 132   // 128 + 4 pad (keeps float4 alignment, breaks conflicts)

__global__ void k_transform(const float* __restrict__ x, float* __restrict__ out) {
    extern __shared__ float smem[];
    float* In  = smem;                    // [64][IN_STRIDE]
    float* Wsh = In + 64 * IN_STRIDE;     // [128][64] flat
    float* red = Wsh + 128 * D;           // [64][17]
    float* nf  = red + 64 * 17;           // [64]

    int tid = threadIdx.x;
    int n0  = blockIdx.x * 64;

    // Load W (flat copy; rows 0..63 = Wm, 64..127 = Ws)
    {
        const float4* wm4 = (const float4*)g_Wm;
        const float4* ws4 = (const float4*)g_Ws;
        float4* w4 = (float4*)Wsh;
        for (int i = tid; i < (D * D) / 4; i += 256) {
            w4[i] = wm4[i];
            w4[i + (D * D) / 4] = ws4[i];
        }
    }
    // Load input tile: In[n][0:64] = h row, In[n][64:128] = x row
    {
        const float4* h4 = (const float4*)g_h;
        const float4* x4 = (const float4*)x;
        for (int i = tid; i < 64 * (D / 4); i += 256) {
            int n = i >> 4, j = i & 15;
            int gn = n0 + n;
            float4 hv = make_float4(0.f, 0.f, 0.f, 0.f);
            float4 xv = hv;
            if (gn < NN) {
                hv = h4[(size_t)gn * (D / 4) + j];
                xv = x4[(size_t)gn * (D / 4) + j];
            }
            *(float4*)&In[n * IN_STRIDE + j * 4]      = hv;
            *(float4*)&In[n * IN_STRIDE + 64 + j * 4] = xv;
        }
    }
    __syncthreads();

    int to = tid & 15;   // col group: cols to*4 .. to*4+3
    int tn = tid >> 4;   // node group: nodes tn*4 .. tn*4+3

    float acc[4][4];
    #pragma unroll
    for (int r = 0; r < 4; r++)
        #pragma unroll
        for (int c = 0; c < 4; c++) acc[r][c] = 0.f;

    const float* a0 = &In[(tn * 4 + 0) * IN_STRIDE];
    const float* a1 = &In[(tn * 4 + 1) * IN_STRIDE];
    const float* a2 = &In[(tn * 4 + 2) * IN_STRIDE];
    const float* a3 = &In[(tn * 4 + 3) * IN_STRIDE];

    #pragma unroll 8
    for (int k = 0; k < 128; k++) {
        float4 b = *(const float4*)&Wsh[k * D + to * 4];
        float v0 = a0[k], v1 = a1[k], v2 = a2[k], v3 = a3[k];
        acc[0][0] = fmaf(v0, b.x, acc[0][0]); acc[0][1] = fmaf(v0, b.y, acc[0][1]);
        acc[0][2] = fmaf(v0, b.z, acc[0][2]); acc[0][3] = fmaf(v0, b.w, acc[0][3]);
        acc[1][0] = fmaf(v1, b.x, acc[1][0]); acc[1][1] = fmaf(v1, b.y, acc[1][1]);
        acc[1][2] = fmaf(v1, b.z, acc[1][2]); acc[1][3] = fmaf(v1, b.w, acc[1][3]);
        acc[2][0] = fmaf(v2, b.x, acc[2][0]); acc[2][1] = fmaf(v2, b.y, acc[2][1]);
        acc[2][2] = fmaf(v2, b.z, acc[2][2]); acc[2][3] = fmaf(v2, b.w, acc[2][3]);
        acc[3][0] = fmaf(v3, b.x, acc[3][0]); acc[3][1] = fmaf(v3, b.y, acc[3][1]);
        acc[3][2] = fmaf(v3, b.z, acc[3][2]); acc[3][3] = fmaf(v3, b.w, acc[3][3]);
    }

    // Epilogue: bias + deg*b_msg, per-node L2 norm, normalized store.
    float bmv[4], bsv[4];
    #pragma unroll
    for (int c = 0; c < 4; c++) {
        bmv[c] = g_bm[to * 4 + c];
        bsv[c] = g_bs[to * 4 + c];
    }

    float vals[4][4];
    #pragma unroll
    for (int r = 0; r < 4; r++) {
        int gn = n0 + tn * 4 + r;
        float dg = (gn < NN) ? g_deg[gn] : 0.f;
        float ss = 0.f;
        #pragma unroll
        for (int c = 0; c < 4; c++) {
            float v = acc[r][c] + dg * bmv[c] + bsv[c];
            vals[r][c] = v;
            ss = fmaf(v, v, ss);
        }
        red[(tn * 4 + r) * 17 + to] = ss;
    }
    __syncthreads();

    if (tid < 64) {
        float s = 0.f;
        #pragma unroll
        for (int t2 = 0; t2 < 16; t2++) s += red[tid * 17 + t2];
        float nrm = sqrtf(s);
        nf[tid] = 1.f / fmaxf(nrm, 1e-12f);
    }
    __syncthreads();

    #pragma unroll
    for (int r = 0; r < 4; r++) {
        int gn = n0 + tn * 4 + r;
        if (gn < NN) {
            float f = nf[tn * 4 + r];
            float4 o4 = make_float4(vals[r][0] * f, vals[r][1] * f,
                                    vals[r][2] * f, vals[r][3] * f);
            *(float4*)&out[(size_t)gn * D + to * 4] = o4;
        }
    }
}

#define SMEM_BYTES ((64 * IN_STRIDE + 128 * D + 64 * 17 + 64) * (int)sizeof(float))

extern "C" void kernel_launch(void* const* d_in, const int* in_sizes, int n_in,
                              void* d_out, int out_size) {
    const float* x   = (const float*)d_in[0];
    const int*   ei  = (const int*)d_in[1];
    const float* bmw = (const float*)d_in[2];
    const float* bmb = (const float*)d_in[3];
    const float* bsw = (const float*)d_in[4];
    const float* bsb = (const float*)d_in[5];
    const float* lc  = (const float*)d_in[6];
    float* out = (float*)d_out;

    void* hptr = nullptr;
    void* dptr = nullptr;
    cudaGetSymbolAddress(&hptr, g_h);
    cudaGetSymbolAddress(&dptr, g_deg);
    cudaMemsetAsync(hptr, 0, sizeof(float) * (size_t)NN * D);
    cudaMemsetAsync(dptr, 0, sizeof(float) * NN);

    k_weights<<<(D * D + D + 255) / 256, 256>>>(bmw, bmb, bsw, bsb, lc);

    unsigned total = (unsigned)NE * 16u;
    k_scatter<<<(total + 255) / 256, 256>>>((const float4*)x, ei);

    cudaFuncSetAttribute(k_transform, cudaFuncAttributeMaxDynamicSharedMemorySize, SMEM_BYTES);
    k_transform<<<(NN + 63) / 64, 256, SMEM_BYTES>>>(x, out);
}